// round 4
// baseline (speedup 1.0000x reference)
#include <cuda_runtime.h>
#include <math.h>

#define NN 8
#define CC 128
#define HH 96
#define WW 96
#define GG 8
#define GCH 16
#define HWSZ (HH*WW)            // 9216
#define NHW (NN*HWSZ)           // 73728
#define OMD 216
#define BNP 224                 // padded N
#define EPST 227                // Ep row stride (bank spread)
#define TILEST 133              // out-tile row stride (odd: conflict-free col reads)
#define GN_EPS 1e-5f

#define REG0 (128*228)          // floats: Bs / Ep region
#define REG1 (128*TILEST)       // floats: tile / As region
#define SMEM_FUSED ((REG0 + REG1) * 4)

// ---------------- device scratch ----------------
__device__ float g_x1[NHW * CC];      // dwconv+bias output, NHWC
__device__ float g_xnhwc[NHW * CC];   // input transposed to NHWC
__device__ float g_omwT[CC * BNP];    // om_w transposed [k][n], zero-padded
__device__ float g_ombp[BNP];         // om_b zero-padded
__device__ float g_sum[NN];
__device__ float g_sumsq[NN];

// ---------------- f32x2 helpers ----------------
__device__ __forceinline__ unsigned long long pack2(float lo, float hi) {
    unsigned long long d;
    asm("mov.b64 %0, {%1, %2};" : "=l"(d) : "f"(lo), "f"(hi));
    return d;
}
__device__ __forceinline__ void unpack2(unsigned long long v, float& lo, float& hi) {
    asm("mov.b64 {%0, %1}, %2;" : "=f"(lo), "=f"(hi) : "l"(v));
}
__device__ __forceinline__ void fma2(unsigned long long& acc, unsigned long long a,
                                     unsigned long long b) {
    asm("fma.rn.f32x2 %0, %1, %2, %0;" : "+l"(acc) : "l"(a), "l"(b));
}

// ---------------- K0: prep (init stats + transpose om_w + pad bias) ----------------
__global__ __launch_bounds__(256) void k_prep(const float* __restrict__ om_w,
                                              const float* __restrict__ om_b) {
    int idx = blockIdx.x * 256 + threadIdx.x;
    if (idx < CC * BNP) {
        int k = idx / BNP;
        int n = idx - k * BNP;
        g_omwT[idx] = (n < OMD) ? om_w[n * CC + k] : 0.f;
    }
    if (idx < BNP) g_ombp[idx] = (idx < OMD) ? om_b[idx] : 0.f;
    if (idx < NN) { g_sum[idx] = 0.f; g_sumsq[idx] = 0.f; }
}

// ---------------- K1: depthwise conv + bias, NHWC transpose, stats ----------------
// grid (H, C/32, N), block (96, 2)
__global__ __launch_bounds__(192) void k_dwconv(const float* __restrict__ x,
                                                const float* __restrict__ dw_w,
                                                const float* __restrict__ dw_b) {
    int h  = blockIdx.x;
    int cb = blockIdx.y;
    int n  = blockIdx.z;
    int w  = threadIdx.x;
    int ty = threadIdx.y;
    int tid = ty * 96 + w;

    __shared__ float s_out[32][97];
    __shared__ float s_in[32][97];
    __shared__ float rbuf[12];

    float s1 = 0.f, s2 = 0.f;

    #pragma unroll 4
    for (int i = 0; i < 16; ++i) {
        int c = cb * 32 + ty * 16 + i;
        const float* xc = x + ((size_t)(n * CC + c)) * HWSZ;
        float wgt[9];
        #pragma unroll
        for (int t = 0; t < 9; ++t) wgt[t] = dw_w[c * 9 + t];
        float acc = dw_b[c];
        float ctr = 0.f;
        #pragma unroll
        for (int dy = -1; dy <= 1; ++dy) {
            int y = h + dy;
            if ((unsigned)y < HH) {
                #pragma unroll
                for (int dx = -1; dx <= 1; ++dx) {
                    int xx = w + dx;
                    if ((unsigned)xx < WW) {
                        float v = xc[y * WW + xx];
                        acc += v * wgt[(dy + 1) * 3 + (dx + 1)];
                        if (dy == 0 && dx == 0) ctr = v;
                    }
                }
            }
        }
        s_out[ty * 16 + i][w] = acc;
        s_in [ty * 16 + i][w] = ctr;
        s1 += acc;
        s2 += acc * acc;
    }

    #pragma unroll
    for (int o = 16; o; o >>= 1) {
        s1 += __shfl_down_sync(0xffffffffu, s1, o);
        s2 += __shfl_down_sync(0xffffffffu, s2, o);
    }
    int wid = tid >> 5, lane = tid & 31;
    if (lane == 0) { rbuf[wid] = s1; rbuf[6 + wid] = s2; }
    __syncthreads();
    if (tid == 0) {
        float a = 0.f, b = 0.f;
        #pragma unroll
        for (int i = 0; i < 6; ++i) { a += rbuf[i]; b += rbuf[6 + i]; }
        atomicAdd(&g_sum[n], a);
        atomicAdd(&g_sumsq[n], b);
    }

    size_t base = ((size_t)(n * HWSZ + h * WW)) * CC + cb * 32;
    for (int idx = tid; idx < 3072; idx += 192) {
        int ww = idx >> 5;
        int cc = idx & 31;
        g_x1   [base + (size_t)ww * CC + cc] = s_out[cc][ww];
        g_xnhwc[base + (size_t)ww * CC + cc] = s_in[cc][ww];
    }
}

// ---------------- K2: fused norm+GELU GEMM (f32x2) + deformable sampling ----------------
// grid 576, block 512. BM=128 pixels (single n per block), full N=216(224).
extern __shared__ float sm[];
__global__ __launch_bounds__(512, 1) void k_fused(const float* __restrict__ gn_w,
                                                  const float* __restrict__ gn_b,
                                                  float* __restrict__ out) {
    float* Bs   = sm;           // [128 k][BNP], then reused as Ep[128 px][EPST]
    float* As   = sm + REG0;    // [16 k][128 rows], inside tile region
    float* tile = sm + REG0;    // [128 px][TILEST]

    const int tid = threadIdx.x;
    const int bm  = blockIdx.x;
    const int tn  = tid & 15;         // 14 cols each
    const int tm  = tid >> 4;         // 4 rows each (0..31)

    // stage all of B^T into smem (coalesced float4)
    {
        const float4* src = (const float4*)g_omwT;
        float4* dst = (float4*)Bs;
        #pragma unroll
        for (int i = 0; i < CC * BNP / 4 / 512; ++i)
            dst[i * 512 + tid] = src[i * 512 + tid];
    }

    // per-sample stats (folded k_stats)
    const int nidx = (bm * 128) / HWSZ;
    const float inv = 1.f / (float)(CC * HWSZ);
    const float mu = g_sum[nidx] * inv;
    const float rs = rsqrtf(g_sumsq[nidx] * inv - mu * mu + GN_EPS);

    // init accumulators from bias
    unsigned long long acc[4][7];
    #pragma unroll
    for (int j = 0; j < 7; ++j) {
        unsigned long long bb = pack2(g_ombp[tn * 14 + 2 * j], g_ombp[tn * 14 + 2 * j + 1]);
        #pragma unroll
        for (int i = 0; i < 4; ++i) acc[i][j] = bb;
    }

    const int c0 = (tid & 3) * 4;
    const int rowa = tid >> 2;        // 0..127

    for (int kc = 0; kc < 8; ++kc) {
        // ---- A chunk (128 rows x 16 k), fused norm + exact GELU ----
        {
            float4 xv = *(const float4*)&g_x1[(size_t)(bm * 128 + rowa) * CC + kc * 16 + c0];
            float vv[4] = {xv.x, xv.y, xv.z, xv.w};
            #pragma unroll
            for (int j = 0; j < 4; ++j) {
                int c = kc * 16 + c0 + j;
                float v = (vv[j] - mu) * rs * gn_w[c] + gn_b[c];
                v = 0.5f * v * (1.0f + erff(v * 0.7071067811865475f));
                As[(c0 + j) * 128 + rowa] = v;
            }
        }
        __syncthreads();
        #pragma unroll
        for (int kk = 0; kk < 16; ++kk) {
            float4 a4 = *(const float4*)&As[kk * 128 + tm * 4];
            unsigned long long a2[4];
            a2[0] = pack2(a4.x, a4.x);
            a2[1] = pack2(a4.y, a4.y);
            a2[2] = pack2(a4.z, a4.z);
            a2[3] = pack2(a4.w, a4.w);
            const unsigned long long* brow =
                (const unsigned long long*)&Bs[(kc * 16 + kk) * BNP + tn * 14];
            #pragma unroll
            for (int j = 0; j < 7; ++j) {
                unsigned long long b2 = brow[j];
                fma2(acc[0][j], a2[0], b2);
                fma2(acc[1][j], a2[1], b2);
                fma2(acc[2][j], a2[2], b2);
                fma2(acc[3][j], a2[3], b2);
            }
        }
        __syncthreads();
    }

    // ---- epilogue: om values into smem (Ep over Bs region) ----
    float* Ep = Bs;
    #pragma unroll
    for (int i = 0; i < 4; ++i) {
        int row = tm * 4 + i;
        #pragma unroll
        for (int j = 0; j < 7; ++j) {
            float lo, hi;
            unpack2(acc[i][j], lo, hi);
            Ep[row * EPST + tn * 14 + 2 * j]     = lo;
            Ep[row * EPST + tn * 14 + 2 * j + 1] = hi;
        }
    }
    __syncthreads();

    // ---- sampling phase: 1024 tasks = 128 pixels x 8 groups, 2 per thread ----
    const int hw0 = bm * 128 - nidx * HWSZ;
    const float* xb = g_xnhwc + (size_t)nidx * HWSZ * CC;

    #pragma unroll
    for (int rep = 0; rep < 2; ++rep) {
        int task = rep * 512 + tid;
        int pixel = task >> 3;
        int g = task & 7;
        int hw = hw0 + pixel;
        int h = hw / WW;
        int w = hw - h * WW;

        const float* omr = &Ep[pixel * EPST + g * 27];
        const int cbase = g * GCH;
        float a0[16];
        #pragma unroll
        for (int i = 0; i < 16; ++i) a0[i] = 0.f;

        #pragma unroll
        for (int k = 0; k < 9; ++k) {
            float offx = omr[2 * k];
            float offy = omr[2 * k + 1];
            float m    = omr[18 + k];
            float ly = (float)(h + (k / 3) - 1) + offy;
            float lx = (float)(w + (k % 3) - 1) + offx;
            float y0f = floorf(ly), x0f = floorf(lx);
            float fy = ly - y0f, fx = lx - x0f;
            int y0 = (int)y0f, x0 = (int)x0f;
            float wts[4];
            wts[0] = (1.f - fy) * (1.f - fx) * m;
            wts[1] = (1.f - fy) * fx * m;
            wts[2] = fy * (1.f - fx) * m;
            wts[3] = fy * fx * m;
            #pragma unroll
            for (int t = 0; t < 4; ++t) {
                int yy = y0 + (t >> 1);
                int xx = x0 + (t & 1);
                if ((unsigned)yy < HH && (unsigned)xx < WW) {
                    float wt = wts[t];
                    const float* src = &xb[(size_t)(yy * WW + xx) * CC + cbase];
                    #pragma unroll
                    for (int q = 0; q < 4; ++q) {
                        float4 v = *(const float4*)(src + 4 * q);
                        a0[4*q+0] = fmaf(wt, v.x, a0[4*q+0]);
                        a0[4*q+1] = fmaf(wt, v.y, a0[4*q+1]);
                        a0[4*q+2] = fmaf(wt, v.z, a0[4*q+2]);
                        a0[4*q+3] = fmaf(wt, v.w, a0[4*q+3]);
                    }
                }
            }
        }
        float* trow = &tile[pixel * TILEST + cbase];
        #pragma unroll
        for (int i = 0; i < 16; ++i) trow[i] = a0[i];   // scalar STS (stride-safe)
    }
    __syncthreads();

    // ---- coalesced NCHW writeout: 128 ch x 128 pixels ----
    float* ob = out + (size_t)nidx * CC * HWSZ + hw0;
    for (int idx = tid; idx < CC * 128; idx += 512) {
        int c = idx >> 7;
        int pp = idx & 127;
        ob[(size_t)c * HWSZ + pp] = tile[pp * TILEST + c];
    }
}

// ---------------- launcher ----------------
extern "C" void kernel_launch(void* const* d_in, const int* in_sizes, int n_in,
                              void* d_out, int out_size) {
    const float* x    = (const float*)d_in[0];
    const float* dw_w = (const float*)d_in[1];
    const float* dw_b = (const float*)d_in[2];
    const float* gn_w = (const float*)d_in[3];
    const float* gn_b = (const float*)d_in[4];
    const float* om_w = (const float*)d_in[5];
    const float* om_b = (const float*)d_in[6];
    float* out = (float*)d_out;

    cudaFuncSetAttribute(k_fused, cudaFuncAttributeMaxDynamicSharedMemorySize, SMEM_FUSED);

    k_prep<<<(CC * BNP + 255) / 256, 256>>>(om_w, om_b);
    dim3 g1(HH, CC / 32, NN), b1(96, 2);
    k_dwconv<<<g1, b1>>>(x, dw_w, dw_b);
    k_fused<<<NHW / 128, 512, SMEM_FUSED>>>(gn_w, gn_b, out);
}

// round 5
// speedup vs baseline: 1.3330x; 1.3330x over previous
#include <cuda_runtime.h>
#include <math.h>

#define NN 8
#define CC 128
#define HH 96
#define WW 96
#define GG 8
#define GCH 16
#define HWSZ (HH*WW)            // 9216
#define NHW (NN*HWSZ)           // 73728
#define OMD 216
#define BNP 224                 // padded N for the GEMM
#define GN_EPS 1e-5f

// ---------------- device scratch ----------------
__device__ float g_x1[NHW * CC];      // dwconv+bias output, NHWC
__device__ float g_xnhwc[NHW * CC];   // input transposed to NHWC
__device__ float g_om[NHW * OMD];     // offsets/masks GEMM output
__device__ float g_omwT[CC * BNP];    // om_w transposed [k][n], zero-padded
__device__ float g_ombp[BNP];         // om_b zero-padded
__device__ float g_sum[NN];
__device__ float g_sumsq[NN];

// ---------------- f32x2 helpers ----------------
__device__ __forceinline__ unsigned long long pack2(float lo, float hi) {
    unsigned long long d;
    asm("mov.b64 %0, {%1, %2};" : "=l"(d) : "f"(lo), "f"(hi));
    return d;
}
__device__ __forceinline__ void unpack2(unsigned long long v, float& lo, float& hi) {
    asm("mov.b64 {%0, %1}, %2;" : "=f"(lo), "=f"(hi) : "l"(v));
}
__device__ __forceinline__ void fma2(unsigned long long& acc, unsigned long long a,
                                     unsigned long long b) {
    asm("fma.rn.f32x2 %0, %1, %2, %0;" : "+l"(acc) : "l"(a), "l"(b));
}

// ---------------- K0: prep (init stats + transpose om_w + pad bias) ----------------
__global__ __launch_bounds__(256) void k_prep(const float* __restrict__ om_w,
                                              const float* __restrict__ om_b) {
    int idx = blockIdx.x * 256 + threadIdx.x;
    if (idx < CC * BNP) {
        int k = idx / BNP;
        int n = idx - k * BNP;
        g_omwT[idx] = (n < OMD) ? om_w[n * CC + k] : 0.f;
    }
    if (idx < BNP) g_ombp[idx] = (idx < OMD) ? om_b[idx] : 0.f;
    if (idx < NN) { g_sum[idx] = 0.f; g_sumsq[idx] = 0.f; }
}

// ---------------- K1: smem-tiled depthwise conv + bias, NHWC transpose, stats --------
// grid (H, C/32, N), block 256. smem: s_in [32 ch][3 rows][101 pad], s_out [32][97].
#define CST 305                 // per-channel stride (305 % 32 = 17, coprime)
#define RST 101                 // per-row stride
#define DW_SMEM ((32*CST + 32*97) * 4)
extern __shared__ float dsm[];
__global__ __launch_bounds__(256) void k_dwconv(const float* __restrict__ x,
                                                const float* __restrict__ dw_w,
                                                const float* __restrict__ dw_b) {
    float* s_in  = dsm;             // addr: c*CST + r*RST + col, col = w+1 (0..97)
    float* s_out = dsm + 32 * CST;  // addr: c*97 + w
    __shared__ float rbuf[16];

    const int h  = blockIdx.x;
    const int cb = blockIdx.y;
    const int n  = blockIdx.z;
    const int tid = threadIdx.x;

    // ---- stage 32 ch x 3 rows x 96 w (coalesced float4; OOB rows -> 0) ----
    #pragma unroll
    for (int it = 0; it < 9; ++it) {
        int idx = tid + it * 256;           // 0..2303
        int c = idx / 72;
        int rem = idx - c * 72;
        int r = rem / 24;
        int q = rem - r * 24;
        int y = h - 1 + r;
        float4 v = {0.f, 0.f, 0.f, 0.f};
        if ((unsigned)y < HH)
            v = *(const float4*)&x[((size_t)(n * CC + cb * 32 + c)) * HWSZ + y * WW + q * 4];
        float* d = &s_in[c * CST + r * RST + 1 + q * 4];
        d[0] = v.x; d[1] = v.y; d[2] = v.z; d[3] = v.w;
    }
    // zero-pad edge columns (kills bounds checks in the stencil)
    if (tid < 96) {
        int c = tid / 3, r = tid - c * 3;
        s_in[c * CST + r * RST + 0]  = 0.f;
        s_in[c * CST + r * RST + 97] = 0.f;
    }
    __syncthreads();

    // ---- stencil: thread = (channel, 12-wide w strip) ----
    const int c  = tid >> 3;
    const int w0 = (tid & 7) * 12;
    const int cg = cb * 32 + c;
    float wgt[9];
    #pragma unroll
    for (int t = 0; t < 9; ++t) wgt[t] = dw_w[cg * 9 + t];
    const float bias = dw_b[cg];
    const float* rowp = &s_in[c * CST];

    float s1 = 0.f, s2 = 0.f;
    #pragma unroll
    for (int i = 0; i < 12; ++i) {
        int w = w0 + i;
        float acc = bias;
        #pragma unroll
        for (int r = 0; r < 3; ++r)
            #pragma unroll
            for (int dx = 0; dx < 3; ++dx)
                acc = fmaf(rowp[r * RST + w + dx], wgt[r * 3 + dx], acc);
        s_out[c * 97 + w] = acc;
        s1 += acc;
        s2 += acc * acc;
    }

    // ---- stats reduction ----
    #pragma unroll
    for (int o = 16; o; o >>= 1) {
        s1 += __shfl_down_sync(0xffffffffu, s1, o);
        s2 += __shfl_down_sync(0xffffffffu, s2, o);
    }
    int wid = tid >> 5, lane = tid & 31;
    if (lane == 0) { rbuf[wid] = s1; rbuf[8 + wid] = s2; }
    __syncthreads();
    if (tid == 0) {
        float a = 0.f, b = 0.f;
        #pragma unroll
        for (int i = 0; i < 8; ++i) { a += rbuf[i]; b += rbuf[8 + i]; }
        atomicAdd(&g_sum[n], a);
        atomicAdd(&g_sumsq[n], b);
    }

    // ---- coalesced NHWC writeout: conv result + center (original x) ----
    size_t base = ((size_t)(n * HWSZ + h * WW)) * CC + cb * 32;
    for (int idx = tid; idx < 3072; idx += 256) {
        int ww = idx >> 5;
        int cc = idx & 31;
        g_x1   [base + (size_t)ww * CC + cc] = s_out[cc * 97 + ww];
        g_xnhwc[base + (size_t)ww * CC + cc] = s_in[cc * CST + RST + 1 + ww];
    }
}

// ---------------- K3: fused norm+GELU + GEMM via fma.rn.f32x2 (R2-proven) ----------------
// grid 576, block 256. BM=128, full N (216 pad 224) per block, all of B in smem.
extern __shared__ float sm_g[];
__global__ __launch_bounds__(256, 1) void k_gemm(const float* __restrict__ gn_w,
                                                 const float* __restrict__ gn_b) {
    float* Bs = sm_g;                 // [128][BNP]
    float* As = sm_g + CC * BNP;      // [16][128]

    const int tid = threadIdx.x;
    const int bm  = blockIdx.x;
    const int tm  = tid & 31;
    const int tn  = tid >> 5;

    {
        const float4* src = (const float4*)g_omwT;
        float4* dst = (float4*)Bs;
        #pragma unroll
        for (int i = 0; i < CC * BNP / 4 / 256; ++i)
            dst[i * 256 + tid] = src[i * 256 + tid];
    }

    // folded stats
    const int nidx = (bm * 128) / HWSZ;
    const float inv = 1.f / (float)(CC * HWSZ);
    const float mu = g_sum[nidx] * inv;
    const float rs = rsqrtf(g_sumsq[nidx] * inv - mu * mu + GN_EPS);

    unsigned long long acc[4][14];
    #pragma unroll
    for (int j = 0; j < 14; ++j) {
        unsigned long long bb = pack2(g_ombp[tn * 28 + 2 * j], g_ombp[tn * 28 + 2 * j + 1]);
        #pragma unroll
        for (int i = 0; i < 4; ++i) acc[i][j] = bb;
    }

    const int c0 = (tid & 3) * 4;
    const int rowb = tid >> 2;

    for (int kc = 0; kc < 8; ++kc) {
        #pragma unroll
        for (int pass = 0; pass < 2; ++pass) {
            int row = pass * 64 + rowb;
            int p = bm * 128 + row;
            float4 xv = *(const float4*)&g_x1[(size_t)p * CC + kc * 16 + c0];
            float vv[4] = {xv.x, xv.y, xv.z, xv.w};
            #pragma unroll
            for (int j = 0; j < 4; ++j) {
                int c = kc * 16 + c0 + j;
                float v = (vv[j] - mu) * rs * gn_w[c] + gn_b[c];
                v = 0.5f * v * (1.0f + erff(v * 0.7071067811865475f));
                As[(c0 + j) * 128 + row] = v;
            }
        }
        __syncthreads();
        #pragma unroll
        for (int kk = 0; kk < 16; ++kk) {
            float4 a4 = *(const float4*)&As[kk * 128 + tm * 4];
            unsigned long long a2[4];
            a2[0] = pack2(a4.x, a4.x);
            a2[1] = pack2(a4.y, a4.y);
            a2[2] = pack2(a4.z, a4.z);
            a2[3] = pack2(a4.w, a4.w);
            const unsigned long long* brow =
                (const unsigned long long*)&Bs[(kc * 16 + kk) * BNP + tn * 28];
            #pragma unroll
            for (int j = 0; j < 14; ++j) {
                unsigned long long b2 = brow[j];
                fma2(acc[0][j], a2[0], b2);
                fma2(acc[1][j], a2[1], b2);
                fma2(acc[2][j], a2[2], b2);
                fma2(acc[3][j], a2[3], b2);
            }
        }
        __syncthreads();
    }

    float* Ep = sm_g;
    #pragma unroll
    for (int i = 0; i < 4; ++i) {
        int row = tm * 4 + i;
        #pragma unroll
        for (int j = 0; j < 14; ++j) {
            float lo, hi;
            unpack2(acc[i][j], lo, hi);
            Ep[row * 227 + tn * 28 + 2 * j]     = lo;
            Ep[row * 227 + tn * 28 + 2 * j + 1] = hi;
        }
    }
    __syncthreads();
    for (int idx = tid; idx < 128 * OMD; idx += 256) {
        int r = idx / OMD;
        int col = idx - r * OMD;
        g_om[(size_t)(bm * 128 + r) * OMD + col] = Ep[r * 227 + col];
    }
}

// ---------------- K4: deformable bilinear sampling + NCHW output (R2-proven) ----------------
extern __shared__ float sm_s[];
__global__ __launch_bounds__(256) void k_sample(float* __restrict__ out) {
    float* s_om = sm_s;                      // [64][220]
    float (*tile)[133] = (float(*)[133])(sm_s + 64 * 220);

    const int tid = threadIdx.x;
    const int gidx = tid >> 2;
    const int l = tid & 3;
    const int pb = blockIdx.x * 64;
    const int p = pb + gidx;
    const int n = p / HWSZ;
    const int rem = p - n * HWSZ;
    const int h = rem / WW;
    const int w = rem - h * WW;

    {
        const float4* src = (const float4*)(g_om + (size_t)pb * OMD);
        for (int idx = tid; idx < 64 * 54; idx += 256) {
            int pix = idx / 54;
            int c4 = idx - pix * 54;
            float4 v = src[pix * 54 + c4];
            *(float4*)&s_om[pix * 220 + c4 * 4] = v;
        }
    }
    __syncthreads();

    const float* xb = g_xnhwc + (size_t)n * HWSZ * CC;
    const float* omr0 = &s_om[gidx * 220];

    for (int g = 0; g < GG; ++g) {
        const float* omr = omr0 + g * 27;
        const int cbase = g * GCH + l * 4;
        float ax = 0.f, ay = 0.f, az = 0.f, aw = 0.f;
        #pragma unroll
        for (int k = 0; k < 9; ++k) {
            float offx = omr[2 * k];
            float offy = omr[2 * k + 1];
            float m    = omr[18 + k];
            float ly = (float)(h + (k / 3) - 1) + offy;
            float lx = (float)(w + (k % 3) - 1) + offx;
            float y0f = floorf(ly), x0f = floorf(lx);
            float fy = ly - y0f, fx = lx - x0f;
            int y0 = (int)y0f, x0 = (int)x0f;
            float w00 = (1.f - fy) * (1.f - fx) * m;
            float w01 = (1.f - fy) * fx * m;
            float w10 = fy * (1.f - fx) * m;
            float w11 = fy * fx * m;
            #pragma unroll
            for (int t = 0; t < 4; ++t) {
                int yy = y0 + (t >> 1);
                int xx = x0 + (t & 1);
                float wt = (t == 0) ? w00 : (t == 1) ? w01 : (t == 2) ? w10 : w11;
                if ((unsigned)yy < HH && (unsigned)xx < WW) {
                    const float4 v = *(const float4*)&xb[(size_t)((yy * WW + xx)) * CC + cbase];
                    ax = fmaf(wt, v.x, ax);
                    ay = fmaf(wt, v.y, ay);
                    az = fmaf(wt, v.z, az);
                    aw = fmaf(wt, v.w, aw);
                }
            }
        }
        tile[gidx][cbase + 0] = ax;
        tile[gidx][cbase + 1] = ay;
        tile[gidx][cbase + 2] = az;
        tile[gidx][cbase + 3] = aw;
    }
    __syncthreads();

    const int hw0 = pb - n * HWSZ;
    float* ob = out + (size_t)n * CC * HWSZ;
    for (int idx = tid; idx < 8192; idx += 256) {
        int c = idx >> 6;
        int pp = idx & 63;
        ob[(size_t)c * HWSZ + hw0 + pp] = tile[pp][c];
    }
}

// ---------------- launcher ----------------
extern "C" void kernel_launch(void* const* d_in, const int* in_sizes, int n_in,
                              void* d_out, int out_size) {
    const float* x    = (const float*)d_in[0];
    const float* dw_w = (const float*)d_in[1];
    const float* dw_b = (const float*)d_in[2];
    const float* gn_w = (const float*)d_in[3];
    const float* gn_b = (const float*)d_in[4];
    const float* om_w = (const float*)d_in[5];
    const float* om_b = (const float*)d_in[6];
    float* out = (float*)d_out;

    const int smem_gemm = (CC * BNP + 16 * CC) * sizeof(float);    // 122880
    const int smem_samp = (64 * 220 + 64 * 133) * sizeof(float);   // 90368
    cudaFuncSetAttribute(k_dwconv, cudaFuncAttributeMaxDynamicSharedMemorySize, DW_SMEM);
    cudaFuncSetAttribute(k_gemm, cudaFuncAttributeMaxDynamicSharedMemorySize, smem_gemm);
    cudaFuncSetAttribute(k_sample, cudaFuncAttributeMaxDynamicSharedMemorySize, smem_samp);

    k_prep<<<(CC * BNP + 255) / 256, 256>>>(om_w, om_b);
    dim3 g1(HH, CC / 32, NN);
    k_dwconv<<<g1, 256, DW_SMEM>>>(x, dw_w, dw_b);
    k_gemm<<<NHW / 128, 256, smem_gemm>>>(gn_w, gn_b);
    k_sample<<<NHW / 64, 256, smem_samp>>>(out);
}